// round 6
// baseline (speedup 1.0000x reference)
#include <cuda_runtime.h>
#include <cuda_bf16.h>

// ---------------------------------------------------------------------------
// Encoder output is DEAD; decoder scan is batch-invariant. Output[b,t,:] = h_t
// of a single 512-step, 66-unit LSTM with the fc feedback folded in:
//   gate_t = A h_{t-1} + bias0,   A = dec_W_ih @ fc_W + dec_W_hh   [264 x 66]
//   bias0  = dec_W_ih @ fc_b + dec_b_ih + dec_b_hh
//   gate_0 = dec_W_ih @ emb[0] + dec_b_ih + dec_b_hh
// ---------------------------------------------------------------------------

#define DEC_H 66
#define GATES 264          // 4*DEC_H
#define A_STRIDE 68        // padded row stride (16B aligned, zero pad)
#define EMBED 128
#define T_STEPS 512

__device__ __align__(16) float g_A[GATES * A_STRIDE];
__device__ float g_bias0[GATES];
__device__ float g_gate0[GATES];
__device__ __align__(16) float g_hseq[T_STEPS * DEC_H];   // 33792 floats

// ---- packed f32x2 + fast tanh helpers ---------------------------------
__device__ __forceinline__ unsigned long long ffma2(unsigned long long a,
                                                    unsigned long long b,
                                                    unsigned long long c) {
    unsigned long long d;
    asm("fma.rn.f32x2 %0, %1, %2, %3;" : "=l"(d) : "l"(a), "l"(b), "l"(c));
    return d;
}
__device__ __forceinline__ unsigned long long fadd2(unsigned long long a,
                                                    unsigned long long b) {
    unsigned long long d;
    asm("add.rn.f32x2 %0, %1, %2;" : "=l"(d) : "l"(a), "l"(b));
    return d;
}
__device__ __forceinline__ float unpack_sum(unsigned long long v) {
    unsigned lo, hi;
    asm("mov.b64 {%0, %1}, %2;" : "=r"(lo), "=r"(hi) : "l"(v));
    return __uint_as_float(lo) + __uint_as_float(hi);
}
__device__ __forceinline__ float tanh_fast(float x) {
    float y;
    asm("tanh.approx.f32 %0, %1;" : "=f"(y) : "f"(x));
    return y;
}

// ---------------------------------------------------------------------------
// Prep: A = W_ih @ fc_W + W_hh (padded), bias0, gate0.  264 blocks x 128 thr.
// 4 independent accumulators + full unroll -> MLP-rich, L2-latency hidden.
// ---------------------------------------------------------------------------
__global__ void prep_kernel(const float* __restrict__ W_ih,
                            const float* __restrict__ W_hh,
                            const float* __restrict__ b_ih,
                            const float* __restrict__ b_hh,
                            const float* __restrict__ fc_W,
                            const float* __restrict__ fc_b,
                            const float* __restrict__ emb) {
    __shared__ float wrow[EMBED];
    const int r = blockIdx.x;
    const int tid = threadIdx.x;
    wrow[tid] = W_ih[r * EMBED + tid];
    __syncthreads();

    if (tid < DEC_H) {
        float a0 = 0.f, a1 = 0.f, a2 = 0.f, a3 = 0.f;
        #pragma unroll
        for (int e = 0; e < EMBED; e += 4) {
            a0 = fmaf(wrow[e + 0], __ldg(&fc_W[(e + 0) * DEC_H + tid]), a0);
            a1 = fmaf(wrow[e + 1], __ldg(&fc_W[(e + 1) * DEC_H + tid]), a1);
            a2 = fmaf(wrow[e + 2], __ldg(&fc_W[(e + 2) * DEC_H + tid]), a2);
            a3 = fmaf(wrow[e + 3], __ldg(&fc_W[(e + 3) * DEC_H + tid]), a3);
        }
        g_A[r * A_STRIDE + tid] = (a0 + a1) + (a2 + a3) + W_hh[r * DEC_H + tid];
    } else if (tid < A_STRIDE) {
        g_A[r * A_STRIDE + tid] = 0.f;   // zero pad
    }

    const int warp = tid >> 5, lane = tid & 31;
    if (warp >= 2) {
        const float* vec = (warp == 2) ? emb : fc_b;   // emb row 0
        float p = 0.f;
        #pragma unroll
        for (int kk = 0; kk < 4; kk++) {
            int e = lane + 32 * kk;
            p = fmaf(wrow[e], __ldg(&vec[e]), p);
        }
        #pragma unroll
        for (int off = 16; off; off >>= 1)
            p += __shfl_xor_sync(0xFFFFFFFFu, p, off);
        if (lane == 0) {
            float db = b_ih[r] + b_hh[r];
            if (warp == 2) g_gate0[r] = p + db;
            else           g_bias0[r] = p + db;
        }
    }
}

// ---------------------------------------------------------------------------
// Decoder: single CTA, 264 threads. thread t -> unit j=t>>2, gate q=t&3,
// gate row r = q*66 + j (torch order i,f,g,o). A row in registers as f32x2
// pairs; h double-buffered in smem -> ONE barrier per step. All
// nonlinearities via single-MUFU tanh.approx:
//   sigmoid(x) = 0.5*tanh(0.5x) + 0.5 ;  tanh(x) = tanh(x)
// expressed branchlessly as  y = fma(tanh(pre*s), m, a)  per-gate constants.
// ---------------------------------------------------------------------------
__global__ void __launch_bounds__(GATES, 1) decoder_kernel() {
    __shared__ __align__(16) float sh_h[2][A_STRIDE];
    const int t = threadIdx.x;
    if (t < A_STRIDE) { sh_h[0][t] = 0.f; sh_h[1][t] = 0.f; }

    const int j = t >> 2;
    const int q = t & 3;
    const int r = q * DEC_H + j;

    unsigned long long a[34];
    {
        const ulonglong2* Ar = reinterpret_cast<const ulonglong2*>(g_A + r * A_STRIDE);
        #pragma unroll
        for (int k = 0; k < 17; k++) {
            ulonglong2 v = Ar[k];
            a[2 * k] = v.x;
            a[2 * k + 1] = v.y;
        }
    }
    const float b0 = g_bias0[r];
    float bias = g_gate0[r];                   // step-0 bias, then b0
    const bool is_g = (q == 2);
    const float ns = is_g ? 1.0f : 0.5f;       // pre-scale for tanh
    const float nm = is_g ? 1.0f : 0.5f;       // post-mul
    const float na = is_g ? 0.0f : 0.5f;       // post-add
    const unsigned mask = 0xFu << (t & 28);    // 4-lane group mask
    float c = 0.f;
    __syncthreads();

    for (int step = 0; step < T_STEPS; step++) {
        const ulonglong2* hv =
            reinterpret_cast<const ulonglong2*>(sh_h[step & 1]);
        // fold bias into acc0's low half (pad lane of hi half stays 0-mult)
        unsigned long long acc0 = (unsigned long long)__float_as_uint(bias);
        unsigned long long acc1 = 0ull, acc2 = 0ull, acc3 = 0ull;
        #pragma unroll
        for (int k = 0; k < 17; k++) {
            ulonglong2 h2 = hv[k];
            if (k & 1) {
                acc2 = ffma2(a[2 * k], h2.x, acc2);
                acc3 = ffma2(a[2 * k + 1], h2.y, acc3);
            } else {
                acc0 = ffma2(a[2 * k], h2.x, acc0);
                acc1 = ffma2(a[2 * k + 1], h2.y, acc1);
            }
        }
        acc0 = fadd2(acc0, acc2);
        acc1 = fadd2(acc1, acc3);
        acc0 = fadd2(acc0, acc1);
        float pre = unpack_sum(acc0);

        float y = fmaf(tanh_fast(pre * ns), nm, na);   // sigmoid or tanh

        float iv = __shfl_sync(mask, y, 0, 4);
        float fv = __shfl_sync(mask, y, 1, 4);
        float gv = __shfl_sync(mask, y, 2, 4);
        float ov = __shfl_sync(mask, y, 3, 4);

        c = fmaf(fv, c, iv * gv);
        float h = ov * tanh_fast(c);

        if (q == 0) {
            sh_h[(step + 1) & 1][j] = h;
            g_hseq[step * DEC_H + j] = h;
        }
        bias = b0;
        __syncthreads();
    }
}

// ---------------------------------------------------------------------------
// Broadcast: out[b,t,j] = hseq[t,j]. grid (33, 128): 8448 float4 per batch
// row, fully coalesced, no integer mod. Source 135KB stays L2-hot.
// ---------------------------------------------------------------------------
__global__ void bcast_kernel(float4* __restrict__ out) {
    const int r = blockIdx.x * blockDim.x + threadIdx.x;   // 0..8447
    const float4* h4 = reinterpret_cast<const float4*>(g_hseq);
    out[blockIdx.y * ((T_STEPS * DEC_H) / 4) + r] = h4[r];
}

extern "C" void kernel_launch(void* const* d_in, const int* in_sizes, int n_in,
                              void* d_out, int out_size) {
    // metadata order: x, c, emb, enc_W_ih, enc_W_hh, enc_b_ih, enc_b_hh,
    //                 dec_W_ih, dec_W_hh, dec_b_ih, dec_b_hh, fc_W, fc_b
    const float* emb  = (const float*)d_in[2];
    const float* dWih = (const float*)d_in[7];
    const float* dWhh = (const float*)d_in[8];
    const float* dbih = (const float*)d_in[9];
    const float* dbhh = (const float*)d_in[10];
    const float* fcW  = (const float*)d_in[11];
    const float* fcb  = (const float*)d_in[12];

    prep_kernel<<<GATES, 128>>>(dWih, dWhh, dbih, dbhh, fcW, fcb, emb);
    decoder_kernel<<<1, GATES>>>();

    dim3 bgrid((T_STEPS * DEC_H) / 4 / 256, 128);   // (33, 128)
    bcast_kernel<<<bgrid, 256>>>((float4*)d_out);
}

// round 7
// speedup vs baseline: 1.0015x; 1.0015x over previous
#include <cuda_runtime.h>
#include <cuda_bf16.h>

// ---------------------------------------------------------------------------
// Encoder output is DEAD; decoder scan is batch-invariant. Output[b,t,:] = h_t
// of a single 512-step, 66-unit LSTM with the fc feedback folded in:
//   gate_t = A h_{t-1} + bias0,   A = dec_W_ih @ fc_W + dec_W_hh   [264 x 66]
//   bias0  = dec_W_ih @ fc_b + dec_b_ih + dec_b_hh
//   gate_0 = dec_W_ih @ emb[0] + dec_b_ih + dec_b_hh
// ---------------------------------------------------------------------------

#define DEC_H 66
#define GATES 264          // 4*DEC_H
#define A_STRIDE 68        // padded row stride (16B aligned, zero pad)
#define EMBED 128
#define T_STEPS 512

__device__ __align__(16) float g_A[GATES * A_STRIDE];
__device__ float g_bias0[GATES];
__device__ float g_gate0[GATES];
__device__ __align__(16) float g_hseq[T_STEPS * DEC_H];   // 33792 floats

// ---- packed f32x2 + fast tanh helpers ---------------------------------
__device__ __forceinline__ unsigned long long ffma2(unsigned long long a,
                                                    unsigned long long b,
                                                    unsigned long long c) {
    unsigned long long d;
    asm("fma.rn.f32x2 %0, %1, %2, %3;" : "=l"(d) : "l"(a), "l"(b), "l"(c));
    return d;
}
__device__ __forceinline__ unsigned long long fadd2(unsigned long long a,
                                                    unsigned long long b) {
    unsigned long long d;
    asm("add.rn.f32x2 %0, %1, %2;" : "=l"(d) : "l"(a), "l"(b));
    return d;
}
__device__ __forceinline__ float unpack_sum(unsigned long long v) {
    unsigned lo, hi;
    asm("mov.b64 {%0, %1}, %2;" : "=r"(lo), "=r"(hi) : "l"(v));
    return __uint_as_float(lo) + __uint_as_float(hi);
}
__device__ __forceinline__ float tanh_fast(float x) {
    float y;
    asm("tanh.approx.f32 %0, %1;" : "=f"(y) : "f"(x));
    return y;
}

// ---------------------------------------------------------------------------
// Prep: A = W_ih @ fc_W + W_hh (padded), bias0, gate0.  264 blocks x 128 thr.
// 4 independent accumulators + full unroll -> MLP-rich, L2-latency hidden.
// ---------------------------------------------------------------------------
__global__ void prep_kernel(const float* __restrict__ W_ih,
                            const float* __restrict__ W_hh,
                            const float* __restrict__ b_ih,
                            const float* __restrict__ b_hh,
                            const float* __restrict__ fc_W,
                            const float* __restrict__ fc_b,
                            const float* __restrict__ emb) {
    __shared__ float wrow[EMBED];
    const int r = blockIdx.x;
    const int tid = threadIdx.x;
    wrow[tid] = W_ih[r * EMBED + tid];
    __syncthreads();

    if (tid < DEC_H) {
        float a0 = 0.f, a1 = 0.f, a2 = 0.f, a3 = 0.f;
        #pragma unroll
        for (int e = 0; e < EMBED; e += 4) {
            a0 = fmaf(wrow[e + 0], __ldg(&fc_W[(e + 0) * DEC_H + tid]), a0);
            a1 = fmaf(wrow[e + 1], __ldg(&fc_W[(e + 1) * DEC_H + tid]), a1);
            a2 = fmaf(wrow[e + 2], __ldg(&fc_W[(e + 2) * DEC_H + tid]), a2);
            a3 = fmaf(wrow[e + 3], __ldg(&fc_W[(e + 3) * DEC_H + tid]), a3);
        }
        g_A[r * A_STRIDE + tid] = (a0 + a1) + (a2 + a3) + W_hh[r * DEC_H + tid];
    } else if (tid < A_STRIDE) {
        g_A[r * A_STRIDE + tid] = 0.f;   // zero pad
    }

    const int warp = tid >> 5, lane = tid & 31;
    if (warp >= 2) {
        const float* vec = (warp == 2) ? emb : fc_b;   // emb row 0
        float p = 0.f;
        #pragma unroll
        for (int kk = 0; kk < 4; kk++) {
            int e = lane + 32 * kk;
            p = fmaf(wrow[e], __ldg(&vec[e]), p);
        }
        #pragma unroll
        for (int off = 16; off; off >>= 1)
            p += __shfl_xor_sync(0xFFFFFFFFu, p, off);
        if (lane == 0) {
            float db = b_ih[r] + b_hh[r];
            if (warp == 2) g_gate0[r] = p + db;
            else           g_bias0[r] = p + db;
        }
    }
}

// ---------------------------------------------------------------------------
// Decoder: single CTA, 264 threads. thread t -> unit j=t>>2, gate q=t&3,
// gate row r = q*66 + j (torch order i,f,g,o). A row in registers as f32x2
// pairs; h double-buffered in smem -> ONE barrier per step. All
// nonlinearities via single-MUFU tanh.approx:
//   sigmoid(x) = 0.5*tanh(0.5x) + 0.5 ;  tanh(x) = tanh(x)
// expressed branchlessly as  y = fma(tanh(pre*s), m, a)  per-gate constants.
// ---------------------------------------------------------------------------
__global__ void __launch_bounds__(GATES, 1) decoder_kernel() {
    __shared__ __align__(16) float sh_h[2][A_STRIDE];
    const int t = threadIdx.x;
    if (t < A_STRIDE) { sh_h[0][t] = 0.f; sh_h[1][t] = 0.f; }

    const int j = t >> 2;
    const int q = t & 3;
    const int r = q * DEC_H + j;

    unsigned long long a[34];
    {
        const ulonglong2* Ar = reinterpret_cast<const ulonglong2*>(g_A + r * A_STRIDE);
        #pragma unroll
        for (int k = 0; k < 17; k++) {
            ulonglong2 v = Ar[k];
            a[2 * k] = v.x;
            a[2 * k + 1] = v.y;
        }
    }
    const float b0 = g_bias0[r];
    float bias = g_gate0[r];                   // step-0 bias, then b0
    const bool is_g = (q == 2);
    const float ns = is_g ? 1.0f : 0.5f;       // pre-scale for tanh
    const float nm = is_g ? 1.0f : 0.5f;       // post-mul
    const float na = is_g ? 0.0f : 0.5f;       // post-add
    const unsigned mask = 0xFu << (t & 28);    // 4-lane group mask
    float c = 0.f;
    __syncthreads();

    for (int step = 0; step < T_STEPS; step++) {
        const ulonglong2* hv =
            reinterpret_cast<const ulonglong2*>(sh_h[step & 1]);
        // fold bias into acc0's low half (pad lane of hi half stays 0-mult)
        unsigned long long acc0 = (unsigned long long)__float_as_uint(bias);
        unsigned long long acc1 = 0ull, acc2 = 0ull, acc3 = 0ull;
        #pragma unroll
        for (int k = 0; k < 17; k++) {
            ulonglong2 h2 = hv[k];
            if (k & 1) {
                acc2 = ffma2(a[2 * k], h2.x, acc2);
                acc3 = ffma2(a[2 * k + 1], h2.y, acc3);
            } else {
                acc0 = ffma2(a[2 * k], h2.x, acc0);
                acc1 = ffma2(a[2 * k + 1], h2.y, acc1);
            }
        }
        acc0 = fadd2(acc0, acc2);
        acc1 = fadd2(acc1, acc3);
        acc0 = fadd2(acc0, acc1);
        float pre = unpack_sum(acc0);

        float y = fmaf(tanh_fast(pre * ns), nm, na);   // sigmoid or tanh

        float iv = __shfl_sync(mask, y, 0, 4);
        float fv = __shfl_sync(mask, y, 1, 4);
        float gv = __shfl_sync(mask, y, 2, 4);
        float ov = __shfl_sync(mask, y, 3, 4);

        c = fmaf(fv, c, iv * gv);
        float h = ov * tanh_fast(c);

        if (q == 0) {
            sh_h[(step + 1) & 1][j] = h;
            g_hseq[step * DEC_H + j] = h;
        }
        bias = b0;
        __syncthreads();
    }
}

// ---------------------------------------------------------------------------
// Broadcast: out[b,t,j] = hseq[t,j]. grid (33, 128): 8448 float4 per batch
// row, fully coalesced, no integer mod. Source 135KB stays L2-hot.
// ---------------------------------------------------------------------------
__global__ void bcast_kernel(float4* __restrict__ out) {
    const int r = blockIdx.x * blockDim.x + threadIdx.x;   // 0..8447
    const float4* h4 = reinterpret_cast<const float4*>(g_hseq);
    out[blockIdx.y * ((T_STEPS * DEC_H) / 4) + r] = h4[r];
}

extern "C" void kernel_launch(void* const* d_in, const int* in_sizes, int n_in,
                              void* d_out, int out_size) {
    // metadata order: x, c, emb, enc_W_ih, enc_W_hh, enc_b_ih, enc_b_hh,
    //                 dec_W_ih, dec_W_hh, dec_b_ih, dec_b_hh, fc_W, fc_b
    const float* emb  = (const float*)d_in[2];
    const float* dWih = (const float*)d_in[7];
    const float* dWhh = (const float*)d_in[8];
    const float* dbih = (const float*)d_in[9];
    const float* dbhh = (const float*)d_in[10];
    const float* fcW  = (const float*)d_in[11];
    const float* fcb  = (const float*)d_in[12];

    prep_kernel<<<GATES, 128>>>(dWih, dWhh, dbih, dbhh, fcW, fcb, emb);
    decoder_kernel<<<1, GATES>>>();

    dim3 bgrid((T_STEPS * DEC_H) / 4 / 256, 128);   // (33, 128)
    bcast_kernel<<<bgrid, 256>>>((float4*)d_out);
}